// round 12
// baseline (speedup 1.0000x reference)
#include <cuda_runtime.h>
#include <cuda_fp16.h>
#include <math.h>
#include <stdint.h>

#define Nn 6000
#define Ee 120000
#define Dd 128
#define Hh 4
#define Cc 384

// ---------------- scratch (device globals) ----------------
__device__ __align__(16) float g_nodes[Nn * Dd];
__device__ __align__(16) float g_eattr[Ee * Dd];
__device__ __align__(16) float g_nupd[Ee * Dd];
__device__ __align__(16) float g_scores[Ee * Hh];
__device__ __align__(16) float g_upd[Nn * Dd];
__device__ __align__(16) float g_dense[Nn * Dd];
// fp16 hi/lo split activations
__device__ __align__(16) __half g_nodesH[Nn * Dd], g_nodesL[Nn * Dd];
__device__ __align__(16) __half g_eatH[Ee * Dd], g_eatL[Ee * Dd];
__device__ __align__(16) __half g_b1H[Ee * Dd], g_b1L[Ee * Dd];
__device__ __align__(16) __half g_b2H[Ee * Dd], g_b2L[Ee * Dd];
__device__ __align__(16) __half g_aggH[Nn * 4 * Dd], g_aggL[Nn * 4 * Dd];
// node projections (fp32) for decomposed feat GEMMs
__device__ __align__(16) float g_sprojS[4 * Nn * Dd], g_sprojT[4 * Nn * Dd];
__device__ __align__(16) float g_projS[Nn * Dd], g_projT[Nn * Dd];
__device__ float g_zeros[512];   // zero-initialized
__device__ int g_cnt[Nn];
__device__ int g_off[Nn + 1];
__device__ int g_cur[Nn];
__device__ int g_csr[Ee];
#define WT_LAYER 557056
__device__ __align__(16) __half g_wT[2 * WT_LAYER];

__device__ __forceinline__ float gelu_f(float x) {
    return 0.5f * x * (1.0f + erff(x * 0.70710678118654752f));
}
__device__ __forceinline__ uint32_t smem_u32(const void* p) {
    uint32_t a;
    asm("{ .reg .u64 t; cvta.to.shared.u64 t, %1; cvt.u32.u64 %0, t; }" : "=r"(a) : "l"(p));
    return a;
}
__device__ __forceinline__ void ldsm4(uint32_t* r, uint32_t addr) {
    asm volatile("ldmatrix.sync.aligned.m8n8.x4.shared.b16 {%0,%1,%2,%3}, [%4];"
                 : "=r"(r[0]), "=r"(r[1]), "=r"(r[2]), "=r"(r[3]) : "r"(addr));
}
__device__ __forceinline__ void mma16816(float* d, const uint32_t* a, const uint32_t* b) {
    asm volatile("mma.sync.aligned.m16n8k16.row.col.f32.f16.f16.f32 "
                 "{%0,%1,%2,%3}, {%4,%5,%6,%7}, {%8,%9}, {%0,%1,%2,%3};"
                 : "+f"(d[0]), "+f"(d[1]), "+f"(d[2]), "+f"(d[3])
                 : "r"(a[0]), "r"(a[1]), "r"(a[2]), "r"(a[3]), "r"(b[0]), "r"(b[1]));
}
__device__ __forceinline__ void split2h(float x, __half& h, __half& l) {
    h = __float2half_rn(x);
    l = __float2half_rn(x - __half2float(h));
}
__device__ __forceinline__ uint32_t packh(__half a, __half b) {
    return ((uint32_t)__half_as_ushort(b) << 16) | __half_as_ushort(a);
}
__device__ __forceinline__ void cp16(uint32_t saddr, const void* g) {
    asm volatile("cp.async.ca.shared.global [%0], [%1], 16;" :: "r"(saddr), "l"(g));
}
#define CP_COMMIT() asm volatile("cp.async.commit_group;" ::: "memory")
#define CP_WAIT1()  asm volatile("cp.async.wait_group 1;" ::: "memory")
#define CP_WAIT0()  asm volatile("cp.async.wait_group 0;" ::: "memory")

// ---------------- HMMA GEMM (fp16 2-pass, cp.async double-buffered) ----------------
// B has independent row stride Bld (for weight-slice GEMMs). Optional per-edge
// gather-add epilogue: addS[srcI[m]*128+n] + addT[snkI[m]*128+n] before activation.
#define PITCH 80
#define ARR 10240
#define BUFSTR 30720
#define SM_PART 61440
#define SM_TOTAL 62464

__global__ void __launch_bounds__(256) gemm_tc(
    int M, int K,
    const __half* __restrict__ AhG, const __half* __restrict__ AlG,
    const __half* __restrict__ BT, int Bld, long long bStrZ,
    const float* __restrict__ bias,
    float* __restrict__ Cout, long long cStrZ,
    __half* __restrict__ CoH, __half* __restrict__ CoL, int ldc,
    int act, int outSplit,
    const float* __restrict__ addS, const float* __restrict__ addT, long long addStrZ,
    const int* __restrict__ srcI, const int* __restrict__ snkI,
    const float* __restrict__ aAv, const float* __restrict__ aAb)
{
    extern __shared__ char sm[];
    const uint32_t sb = smem_u32(sm);
    const int tid = threadIdx.x, wid = tid >> 5, lane = tid & 31;
    const int m0 = blockIdx.y * 128, n0 = blockIdx.x * 128, z = blockIdx.z;
    if (z) {
        BT += (size_t)z * bStrZ;
        bias += z * 128;
        Cout += (size_t)z * cStrZ;
        if (aAv) aAv += z * 128;
        if (addS) { addS += (size_t)z * addStrZ; addT += (size_t)z * addStrZ; }
    }
    const int mrow0 = (wid & 3) * 32;
    const int ncol0 = (wid >> 2) * 64;
    const int rowoff = ((lane >> 3) & 1) * 8 + (lane & 7);
    const int coloff = (lane >> 4) * 8;

    const int lr0 = tid >> 2, lg0 = (tid & 3) << 3;
    const int lr1 = (tid + 256) >> 2, lg1 = ((tid + 256) & 3) << 3;

    auto issue_chunk = [&](int c) {
        const uint32_t bb = sb + (c & 1) * BUFSTR;
        const int k0 = c << 5;
#pragma unroll
        for (int it = 0; it < 2; ++it) {
            int r = it ? lr1 : lr0, g = it ? lg1 : lg0;
            int mm = m0 + r; if (mm >= M) mm = M - 1;
            int kg = k0 + g;
            uint32_t off = (uint32_t)(r * PITCH + g * 2);
            cp16(bb + off, AhG + (size_t)mm * K + kg);
            cp16(bb + ARR + off, AlG + (size_t)mm * K + kg);
        }
#pragma unroll
        for (int it = 0; it < 2; ++it) {
            int r = it ? lr1 : lr0, g = it ? lg1 : lg0;
            size_t so = (size_t)(n0 + r) * Bld + k0 + g;
            uint32_t off = (uint32_t)(r * PITCH + g * 2);
            cp16(bb + 2 * ARR + off, BT + so);
        }
        CP_COMMIT();
    };

    float acc[2][8][4];
#pragma unroll
    for (int i = 0; i < 2; i++)
#pragma unroll
        for (int j = 0; j < 8; j++)
#pragma unroll
            for (int q = 0; q < 4; q++) acc[i][j][q] = 0.f;

    const int nCh = K >> 5;
    issue_chunk(0);
    for (int c = 0; c < nCh; ++c) {
        if (c + 1 < nCh) { issue_chunk(c + 1); CP_WAIT1(); }
        else CP_WAIT0();
        __syncthreads();
        const uint32_t bb = sb + (c & 1) * BUFSTR;
#pragma unroll
        for (int ks = 0; ks < 2; ++ks) {
            const uint32_t kb = (uint32_t)((ks * 16 + coloff) * 2);
            uint32_t ah[2][4], al[2][4];
#pragma unroll
            for (int ma = 0; ma < 2; ++ma) {
                uint32_t ro = (uint32_t)((mrow0 + ma * 16 + rowoff) * PITCH) + kb;
                ldsm4(ah[ma], bb + ro);
                ldsm4(al[ma], bb + ARR + ro);
            }
            uint32_t bh[8][2];
#pragma unroll
            for (int ng = 0; ng < 4; ++ng) {
                uint32_t ro = (uint32_t)((ncol0 + ng * 16 + rowoff) * PITCH) + kb;
                uint32_t t[4];
                ldsm4(t, bb + 2 * ARR + ro);
                bh[2 * ng][0] = t[0]; bh[2 * ng][1] = t[2];
                bh[2 * ng + 1][0] = t[1]; bh[2 * ng + 1][1] = t[3];
            }
#pragma unroll
            for (int ma = 0; ma < 2; ++ma)
#pragma unroll
                for (int na = 0; na < 8; ++na) mma16816(acc[ma][na], ah[ma], bh[na]);
#pragma unroll
            for (int ma = 0; ma < 2; ++ma)
#pragma unroll
                for (int na = 0; na < 8; ++na) mma16816(acc[ma][na], al[ma], bh[na]);
        }
        __syncthreads();
    }

    // ---- epilogue ----
    float (*part)[2] = (float(*)[2])(sm + SM_PART);
    const int qr = lane >> 2, qc = (lane & 3) * 2;

    // gather bases (per fragment row); clamped rows read valid memory, never stored
    int sA[2], tA[2], sB[2], tB[2];
    if (addS) {
#pragma unroll
        for (int ma = 0; ma < 2; ++ma) {
            int mA = m0 + mrow0 + ma * 16 + qr; if (mA >= M) mA = M - 1;
            int mB = m0 + mrow0 + ma * 16 + 8 + qr; if (mB >= M) mB = M - 1;
            sA[ma] = srcI[mA] * 128; tA[ma] = snkI[mA] * 128;
            sB[ma] = srcI[mB] * 128; tB[ma] = snkI[mB] * 128;
        }
    }

    if (act == 2) {
        const int nh = wid >> 2;
        float s[2][2] = {{0.f, 0.f}, {0.f, 0.f}};
#pragma unroll
        for (int ma = 0; ma < 2; ++ma)
#pragma unroll
            for (int na = 0; na < 8; ++na) {
                int n = ncol0 + na * 8 + qc;
#pragma unroll
                for (int j = 0; j < 2; ++j) {
                    float a0 = addS[sA[ma] + n + j] + addT[tA[ma] + n + j];
                    float a1 = addS[sB[ma] + n + j] + addT[tB[ma] + n + j];
                    float v0 = acc[ma][na][j] + bias[n + j] + a0;
                    v0 = v0 > 0.f ? v0 : 0.2f * v0;
                    s[ma][0] += v0 * aAv[n + j];
                    float v1 = acc[ma][na][2 + j] + bias[n + j] + a1;
                    v1 = v1 > 0.f ? v1 : 0.2f * v1;
                    s[ma][1] += v1 * aAv[n + j];
                }
            }
#pragma unroll
        for (int ma = 0; ma < 2; ++ma)
#pragma unroll
            for (int g = 0; g < 2; ++g) {
                s[ma][g] += __shfl_xor_sync(0xffffffffu, s[ma][g], 1);
                s[ma][g] += __shfl_xor_sync(0xffffffffu, s[ma][g], 2);
            }
        if ((lane & 3) == 0) {
#pragma unroll
            for (int ma = 0; ma < 2; ++ma) {
                part[mrow0 + ma * 16 + qr][nh] = s[ma][0];
                part[mrow0 + ma * 16 + 8 + qr][nh] = s[ma][1];
            }
        }
        __syncthreads();
        if (tid < 128) {
            int m = m0 + tid;
            if (m < M) Cout[(size_t)m * 4 + z] = part[tid][0] + part[tid][1] + aAb[z];
        }
        return;
    }
#pragma unroll
    for (int ma = 0; ma < 2; ++ma) {
        int mA = m0 + mrow0 + ma * 16 + qr;
        int mB = mA + 8;
#pragma unroll
        for (int na = 0; na < 8; ++na) {
            int n = n0 + ncol0 + na * 8 + qc;
            float2 oA, oB;
            oA.x = acc[ma][na][0] + bias[n];
            oA.y = acc[ma][na][1] + bias[n + 1];
            oB.x = acc[ma][na][2] + bias[n];
            oB.y = acc[ma][na][3] + bias[n + 1];
            if (addS) {
                oA.x += addS[sA[ma] + n] + addT[tA[ma] + n];
                oA.y += addS[sA[ma] + n + 1] + addT[tA[ma] + n + 1];
                oB.x += addS[sB[ma] + n] + addT[tB[ma] + n];
                oB.y += addS[sB[ma] + n + 1] + addT[tB[ma] + n + 1];
            }
            if (act == 1) {
                oA.x = gelu_f(oA.x); oA.y = gelu_f(oA.y);
                oB.x = gelu_f(oB.x); oB.y = gelu_f(oB.y);
            }
            if (outSplit) {
                __half h0, l0, h1, l1;
                if (mA < M) {
                    split2h(oA.x, h0, l0); split2h(oA.y, h1, l1);
                    *(uint32_t*)(CoH + (size_t)mA * ldc + n) = packh(h0, h1);
                    *(uint32_t*)(CoL + (size_t)mA * ldc + n) = packh(l0, l1);
                }
                if (mB < M) {
                    split2h(oB.x, h0, l0); split2h(oB.y, h1, l1);
                    *(uint32_t*)(CoH + (size_t)mB * ldc + n) = packh(h0, h1);
                    *(uint32_t*)(CoL + (size_t)mB * ldc + n) = packh(l0, l1);
                }
            } else {
                if (mA < M) *(float2*)(Cout + (size_t)mA * ldc + n) = oA;
                if (mB < M) *(float2*)(Cout + (size_t)mB * ldc + n) = oB;
            }
        }
    }
}

// ---------------- weight transpose to fp16 ----------------
struct TEnt { const float* src; int dstOff; int K; int N; };
struct TTab { TEnt e[26]; };
__global__ void tsplit_k(TTab tab) {
    TEnt E = tab.e[blockIdx.y];
    int i = blockIdx.x * 256 + threadIdx.x;
    int total = E.K * E.N;
    if (i >= total) return;
    int k = i / E.N, n = i % E.N;
    g_wT[E.dstOff + (size_t)n * E.K + k] = __float2half_rn(E.src[i]);
}

// ---------------- setup ----------------
__global__ void embed_k(const int* __restrict__ seq, const float* __restrict__ emb) {
    int i = blockIdx.x * 256 + threadIdx.x;
    if (i < Nn * 128) {
        int nidx = i >> 7, d = i & 127;
        float x = emb[seq[nidx] * 128 + d];
        g_nodes[i] = x;
        __half h, l;
        split2h(x, h, l);
        g_nodesH[i] = h; g_nodesL[i] = l;
    }
}
__global__ void rbf_k(const float* __restrict__ dist, const float* __restrict__ W,
                      const float* __restrict__ b) {
    __shared__ float r[16];
    int e = blockIdx.x;
    int t = threadIdx.x;
    if (t < 16) {
        float mu = 2.0f + (20.0f / 15.0f) * (float)t;
        float x = (dist[e] - mu) * (1.0f / 1.25f);
        r[t] = expf(-x * x) + 1e-8f;
    }
    __syncthreads();
    float s = b[t];
#pragma unroll
    for (int j = 0; j < 16; j++) s += r[j] * W[j * 128 + t];
    long long i = (long long)e * 128 + t;
    g_eattr[i] = s;
    __half h, l;
    split2h(s, h, l);
    g_eatH[i] = h; g_eatL[i] = l;
}

// ---------------- CSR ----------------
__global__ void zero_cnt_k() {
    int i = blockIdx.x * 256 + threadIdx.x;
    if (i < Nn) g_cnt[i] = 0;
}
__global__ void count_k(const int* __restrict__ snk) {
    int e = blockIdx.x * 256 + threadIdx.x;
    if (e < Ee) atomicAdd(&g_cnt[snk[e]], 1);
}
__global__ void __launch_bounds__(1024) scan_k() {
    __shared__ int s[1024];
    int t = threadIdx.x;
    const int CH = (Nn + 1023) / 1024;
    int st = t * CH;
    int en = st + CH; if (en > Nn) en = Nn; if (st > Nn) st = Nn;
    int loc = 0;
    for (int i = st; i < en; i++) loc += g_cnt[i];
    s[t] = loc;
    __syncthreads();
    for (int d = 1; d < 1024; d <<= 1) {
        int v = (t >= d) ? s[t - d] : 0;
        __syncthreads();
        s[t] += v;
        __syncthreads();
    }
    int run = (t == 0) ? 0 : s[t - 1];
    for (int i = st; i < en; i++) {
        g_off[i] = run; g_cur[i] = run; run += g_cnt[i];
    }
    if (t == 1023) g_off[Nn] = s[1023];
}
__global__ void place_k(const int* __restrict__ snk) {
    int e = blockIdx.x * 256 + threadIdx.x;
    if (e < Ee) {
        int p = atomicAdd(&g_cur[snk[e]], 1);
        g_csr[p] = e;
    }
}

// ---------------- per-node softmax + aggregation ----------------
__global__ void __launch_bounds__(128) agg_k() {
    __shared__ float red[4][128];
    int n = blockIdx.x, t = threadIdx.x;
    int beg = g_off[n], end = g_off[n + 1];
    const float4* sc4 = (const float4*)g_scores;

    float mx[4] = {-1e30f, -1e30f, -1e30f, -1e30f};
    for (int i = beg + t; i < end; i += 128) {
        float4 s = sc4[g_csr[i]];
        mx[0] = fmaxf(mx[0], s.x); mx[1] = fmaxf(mx[1], s.y);
        mx[2] = fmaxf(mx[2], s.z); mx[3] = fmaxf(mx[3], s.w);
    }
#pragma unroll
    for (int h = 0; h < 4; h++) red[h][t] = mx[h];
    __syncthreads();
    for (int s = 64; s > 0; s >>= 1) {
        if (t < s)
#pragma unroll
            for (int h = 0; h < 4; h++) red[h][t] = fmaxf(red[h][t], red[h][t + s]);
        __syncthreads();
    }
    float mxf[4];
#pragma unroll
    for (int h = 0; h < 4; h++) mxf[h] = red[h][0];
    __syncthreads();

    float sm[4] = {0.f, 0.f, 0.f, 0.f};
    for (int i = beg + t; i < end; i += 128) {
        float4 s = sc4[g_csr[i]];
        sm[0] += expf(s.x - mxf[0]) + 1e-12f;
        sm[1] += expf(s.y - mxf[1]) + 1e-12f;
        sm[2] += expf(s.z - mxf[2]) + 1e-12f;
        sm[3] += expf(s.w - mxf[3]) + 1e-12f;
    }
#pragma unroll
    for (int h = 0; h < 4; h++) red[h][t] = sm[h];
    __syncthreads();
    for (int s = 64; s > 0; s >>= 1) {
        if (t < s)
#pragma unroll
            for (int h = 0; h < 4; h++) red[h][t] += red[h][t + s];
        __syncthreads();
    }
    float nrm[4];
#pragma unroll
    for (int h = 0; h < 4; h++) nrm[h] = red[h][0];

    float acc[4] = {0.f, 0.f, 0.f, 0.f};
    for (int i = beg; i < end; i++) {
        int e = g_csr[i];
        float4 s = sc4[e];
        float a0 = expf(s.x - mxf[0]) / nrm[0];
        float a1 = expf(s.y - mxf[1]) / nrm[1];
        float a2 = expf(s.z - mxf[2]) / nrm[2];
        float a3 = expf(s.w - mxf[3]) / nrm[3];
        float v = g_nupd[(long long)e * 128 + t];
        acc[0] += a0 * v; acc[1] += a1 * v; acc[2] += a2 * v; acc[3] += a3 * v;
    }
    long long base = (long long)n * 512;
#pragma unroll
    for (int h = 0; h < 4; h++) {
        __half hh, ll;
        split2h(acc[h], hh, ll);
        g_aggH[base + h * 128 + t] = hh;
        g_aggL[base + h * 128 + t] = ll;
    }
}

// ---------------- LayerNorm (+ optional split out) ----------------
__global__ void __launch_bounds__(128) ln_k(const float* __restrict__ a,
                                            const float* __restrict__ r,
                                            const float* __restrict__ g,
                                            const float* __restrict__ b,
                                            float* __restrict__ out,
                                            __half* __restrict__ oh,
                                            __half* __restrict__ ol) {
    int row = blockIdx.x, t = threadIdx.x;
    __shared__ float sh[8];
    long long base = (long long)row * 128;
    float x = a[base + t] + r[base + t];
    float s = x;
#pragma unroll
    for (int o = 16; o; o >>= 1) s += __shfl_xor_sync(0xffffffffu, s, o);
    if ((t & 31) == 0) sh[t >> 5] = s;
    __syncthreads();
    float mean = (sh[0] + sh[1] + sh[2] + sh[3]) * (1.0f / 128.0f);
    float d = x - mean;
    float v = d * d;
#pragma unroll
    for (int o = 16; o; o >>= 1) v += __shfl_xor_sync(0xffffffffu, v, o);
    if ((t & 31) == 0) sh[4 + (t >> 5)] = v;
    __syncthreads();
    float var = (sh[4] + sh[5] + sh[6] + sh[7]) * (1.0f / 128.0f);
    float y = d * rsqrtf(var + 1e-5f) * g[t] + b[t];
    out[base + t] = y;
    if (oh) {
        __half hh, ll;
        split2h(y, hh, ll);
        oh[base + t] = hh; ol[base + t] = ll;
    }
}

// ---------------- copy out ----------------
__global__ void out_k(float* __restrict__ out) {
    long long i = (long long)blockIdx.x * 256 + threadIdx.x;
    const long long nTot = (long long)Nn * 128;
    const long long tot = nTot + (long long)Ee * 128;
    if (i < nTot) out[i] = g_nodes[i];
    else if (i < tot) out[i] = g_eattr[i - nTot];
}

// ---------------- host ----------------
extern "C" void kernel_launch(void* const* d_in, const int* in_sizes, int n_in,
                              void* d_out, int out_size) {
    const int* seq = (const int*)d_in[0];
    const int* eidx = (const int*)d_in[1];
    const int* srcI = eidx;
    const int* snkI = eidx + Ee;
    const float* dist = (const float*)d_in[2];
    const float* seq_embed = (const float*)d_in[3];
    const float* edge_lin_W = (const float*)d_in[4];
    const float* edge_lin_b = (const float*)d_in[5];
    const float* aW_W = (const float*)d_in[6];
    const float* aW_b = (const float*)d_in[7];
    const float* aA_W = (const float*)d_in[8];
    const float* aA_b = (const float*)d_in[9];
    const float* nmlp_W1 = (const float*)d_in[10];
    const float* nmlp_b1 = (const float*)d_in[11];
    const float* nmlp_W2 = (const float*)d_in[12];
    const float* nmlp_b2 = (const float*)d_in[13];
    const float* nmlp_W3 = (const float*)d_in[14];
    const float* nmlp_b3 = (const float*)d_in[15];
    const float* dmlp_W1 = (const float*)d_in[16];
    const float* dmlp_b1 = (const float*)d_in[17];
    const float* dmlp_W2 = (const float*)d_in[18];
    const float* dmlp_b2 = (const float*)d_in[19];
    const float* emlp_W1 = (const float*)d_in[20];
    const float* emlp_b1 = (const float*)d_in[21];
    const float* emlp_W2 = (const float*)d_in[22];
    const float* emlp_b2 = (const float*)d_in[23];
    const float* emlp_W3 = (const float*)d_in[24];
    const float* emlp_b3 = (const float*)d_in[25];
    const float* aggr_W = (const float*)d_in[26];
    const float* aggr_b = (const float*)d_in[27];
    const float* n1_g = (const float*)d_in[28];
    const float* n1_b = (const float*)d_in[29];
    const float* e_g = (const float*)d_in[30];
    const float* e_b = (const float*)d_in[31];

    float *p_nodes, *p_eattr, *p_nupd, *p_scores, *p_upd, *p_dense;
    float *pSS, *pST, *pPS, *pPT, *pZero;
    __half *pW, *pNh, *pNl, *pEh, *pEl, *pB1h, *pB1l, *pB2h, *pB2l, *pAgh, *pAgl;
    cudaGetSymbolAddress((void**)&p_nodes, g_nodes);
    cudaGetSymbolAddress((void**)&p_eattr, g_eattr);
    cudaGetSymbolAddress((void**)&p_nupd, g_nupd);
    cudaGetSymbolAddress((void**)&p_scores, g_scores);
    cudaGetSymbolAddress((void**)&p_upd, g_upd);
    cudaGetSymbolAddress((void**)&p_dense, g_dense);
    cudaGetSymbolAddress((void**)&pSS, g_sprojS);
    cudaGetSymbolAddress((void**)&pST, g_sprojT);
    cudaGetSymbolAddress((void**)&pPS, g_projS);
    cudaGetSymbolAddress((void**)&pPT, g_projT);
    cudaGetSymbolAddress((void**)&pZero, g_zeros);
    cudaGetSymbolAddress((void**)&pW, g_wT);
    cudaGetSymbolAddress((void**)&pNh, g_nodesH);
    cudaGetSymbolAddress((void**)&pNl, g_nodesL);
    cudaGetSymbolAddress((void**)&pEh, g_eatH);
    cudaGetSymbolAddress((void**)&pEl, g_eatL);
    cudaGetSymbolAddress((void**)&pB1h, g_b1H);
    cudaGetSymbolAddress((void**)&pB1l, g_b1L);
    cudaGetSymbolAddress((void**)&pB2h, g_b2H);
    cudaGetSymbolAddress((void**)&pB2l, g_b2L);
    cudaGetSymbolAddress((void**)&pAgh, g_aggH);
    cudaGetSymbolAddress((void**)&pAgl, g_aggL);

    cudaFuncSetAttribute(gemm_tc, cudaFuncAttributeMaxDynamicSharedMemorySize, SM_TOTAL);

    TTab tab;
    {
        int idx = 0;
        for (int l = 0; l < 2; l++) {
            int lb = l * WT_LAYER;
            for (int h = 0; h < 4; h++)
                tab.e[idx++] = { aW_W + (size_t)(l * 4 + h) * 384 * 128, lb + h * 49152, 384, 128 };
            tab.e[idx++] = { nmlp_W1 + (size_t)l * 384 * 128, lb + 196608, 384, 128 };
            tab.e[idx++] = { nmlp_W2 + (size_t)l * 128 * 128, lb + 245760, 128, 128 };
            tab.e[idx++] = { nmlp_W3 + (size_t)l * 128 * 128, lb + 262144, 128, 128 };
            tab.e[idx++] = { aggr_W + (size_t)l * 512 * 128, lb + 278528, 512, 128 };
            tab.e[idx++] = { dmlp_W1 + (size_t)l * 128 * 512, lb + 344064, 128, 512 };
            tab.e[idx++] = { dmlp_W2 + (size_t)l * 512 * 128, lb + 409600, 512, 128 };
            tab.e[idx++] = { emlp_W1 + (size_t)l * 384 * 128, lb + 475136, 384, 128 };
            tab.e[idx++] = { emlp_W2 + (size_t)l * 128 * 128, lb + 524288, 128, 128 };
            tab.e[idx++] = { emlp_W3 + (size_t)l * 128 * 128, lb + 540672, 128, 128 };
        }
    }

    // full generic launcher
    auto G = [&](int M, int K, int nTile, int zDim,
                 const __half* Ah, const __half* Al,
                 const __half* B, int Bld, long long bStrZ,
                 const float* bias, float* Cp, long long cStrZ,
                 __half* CoH, __half* CoL, int ldc, int act, int osplit,
                 const float* addS, const float* addT, long long addStrZ,
                 const float* aAv, const float* aAb) {
        dim3 g(nTile, (M + 127) / 128, zDim);
        gemm_tc<<<g, 256, SM_TOTAL>>>(M, K, Ah, Al, B, Bld, bStrZ, bias, Cp, cStrZ,
                                      CoH, CoL, ldc, act, osplit,
                                      addS, addT, addStrZ, srcI, snkI, aAv, aAb);
    };

    tsplit_k<<<dim3(256, 26), 256>>>(tab);
    embed_k<<<(Nn * 128 + 255) / 256, 256>>>(seq, seq_embed);
    rbf_k<<<Ee, 128>>>(dist, edge_lin_W, edge_lin_b);
    zero_cnt_k<<<(Nn + 255) / 256, 256>>>();
    count_k<<<(Ee + 255) / 256, 256>>>(snkI);
    scan_k<<<1, 1024>>>();
    place_k<<<(Ee + 255) / 256, 256>>>(snkI);

    const long long HW = 49152;          // per-head weight stride (elements)
    const long long SPROJ = (long long)Nn * 128;

    for (int l = 0; l < 2; l++) {
        long long lb = (long long)l * WT_LAYER;
        // --- score: node projections (src, snk) then edge GEMM (K=128) with gather ---
        G(Nn, 128, 1, 4, pNh, pNl, pW + lb, 384, HW, pZero, pSS, SPROJ,
          nullptr, nullptr, 128, 0, 0, nullptr, nullptr, 0, nullptr, nullptr);
        G(Nn, 128, 1, 4, pNh, pNl, pW + lb + 128, 384, HW, pZero, pST, SPROJ,
          nullptr, nullptr, 128, 0, 0, nullptr, nullptr, 0, nullptr, nullptr);
        G(Ee, 128, 1, 4, pEh, pEl, pW + lb + 256, 384, HW, aW_b + l * 512, p_scores, 0,
          nullptr, nullptr, 128, 2, 0, pSS, pST, SPROJ, aA_W + l * 512, aA_b + l * 4);
        // --- nmlp: node projections + edge chain ---
        G(Nn, 128, 1, 1, pNh, pNl, pW + lb + 196608, 384, 0, pZero, pPS, 0,
          nullptr, nullptr, 128, 0, 0, nullptr, nullptr, 0, nullptr, nullptr);
        G(Nn, 128, 1, 1, pNh, pNl, pW + lb + 196608 + 128, 384, 0, pZero, pPT, 0,
          nullptr, nullptr, 128, 0, 0, nullptr, nullptr, 0, nullptr, nullptr);
        G(Ee, 128, 1, 1, pEh, pEl, pW + lb + 196608 + 256, 384, 0, nmlp_b1 + l * 128, nullptr, 0,
          pB1h, pB1l, 128, 1, 1, pPS, pPT, 0, nullptr, nullptr);
        G(Ee, 128, 1, 1, pB1h, pB1l, pW + lb + 245760, 128, 0, nmlp_b2 + l * 128, nullptr, 0,
          pB2h, pB2l, 128, 1, 1, nullptr, nullptr, 0, nullptr, nullptr);
        G(Ee, 128, 1, 1, pB2h, pB2l, pW + lb + 262144, 128, 0, nmlp_b3 + l * 128, p_nupd, 0,
          nullptr, nullptr, 128, 0, 0, nullptr, nullptr, 0, nullptr, nullptr);
        agg_k<<<Nn, 128>>>();
        G(Nn, 512, 1, 1, pAgh, pAgl, pW + lb + 278528, 512, 0, aggr_b + l * 128, p_upd, 0,
          nullptr, nullptr, 128, 0, 0, nullptr, nullptr, 0, nullptr, nullptr);
        ln_k<<<Nn, 128>>>(p_nodes, p_upd, n1_g + l * 128, n1_b + l * 128, p_nodes, pNh, pNl);
        G(Nn, 128, 4, 1, pNh, pNl, pW + lb + 344064, 128, 0, dmlp_b1 + l * 512, nullptr, 0,
          pB1h, pB1l, 512, 1, 1, nullptr, nullptr, 0, nullptr, nullptr);
        G(Nn, 512, 1, 1, pB1h, pB1l, pW + lb + 409600, 512, 0, dmlp_b2 + l * 128, p_dense, 0,
          nullptr, nullptr, 128, 0, 0, nullptr, nullptr, 0, nullptr, nullptr);
        ln_k<<<Nn, 128>>>(p_dense, p_upd, n1_g + l * 128, n1_b + l * 128, p_nodes, pNh, pNl);
        // --- emlp: node projections (post-update nodes) + edge chain ---
        G(Nn, 128, 1, 1, pNh, pNl, pW + lb + 475136, 384, 0, pZero, pPS, 0,
          nullptr, nullptr, 128, 0, 0, nullptr, nullptr, 0, nullptr, nullptr);
        G(Nn, 128, 1, 1, pNh, pNl, pW + lb + 475136 + 128, 384, 0, pZero, pPT, 0,
          nullptr, nullptr, 128, 0, 0, nullptr, nullptr, 0, nullptr, nullptr);
        G(Ee, 128, 1, 1, pEh, pEl, pW + lb + 475136 + 256, 384, 0, emlp_b1 + l * 128, nullptr, 0,
          pB1h, pB1l, 128, 1, 1, pPS, pPT, 0, nullptr, nullptr);
        G(Ee, 128, 1, 1, pB1h, pB1l, pW + lb + 524288, 128, 0, emlp_b2 + l * 128, nullptr, 0,
          pB2h, pB2l, 128, 1, 1, nullptr, nullptr, 0, nullptr, nullptr);
        G(Ee, 128, 1, 1, pB2h, pB2l, pW + lb + 540672, 128, 0, emlp_b3 + l * 128, p_nupd, 0,
          nullptr, nullptr, 128, 0, 0, nullptr, nullptr, 0, nullptr, nullptr);
        ln_k<<<Ee, 128>>>(p_eattr, p_nupd, e_g + l * 128, e_b + l * 128, p_eattr,
                          l == 0 ? pEh : nullptr, l == 0 ? pEl : nullptr);
    }

    long long tot = (long long)Nn * 128 + (long long)Ee * 128;
    out_k<<<(int)((tot + 255) / 256), 256>>>((float*)d_out);
}

// round 13
// speedup vs baseline: 1.1547x; 1.1547x over previous
#include <cuda_runtime.h>
#include <cuda_fp16.h>
#include <math.h>
#include <stdint.h>

#define Nn 6000
#define Ee 120000
#define Dd 128
#define Hh 4
#define Cc 384

// ---------------- scratch (device globals) ----------------
__device__ __align__(16) float g_nodes[Nn * Dd];
__device__ __align__(16) float g_eattr[Ee * Dd];
__device__ __align__(16) float g_nupd[Ee * Dd];
__device__ __align__(16) float g_scores[Ee * Hh];
__device__ __align__(16) float g_upd[Nn * Dd];
__device__ __align__(16) float g_dense[Nn * Dd];
__device__ __align__(16) __half g_nodesH[Nn * Dd], g_nodesL[Nn * Dd];
__device__ __align__(16) __half g_eatH[Ee * Dd], g_eatL[Ee * Dd];
__device__ __align__(16) __half g_b1H[Ee * Dd], g_b1L[Ee * Dd];
__device__ __align__(16) __half g_b2H[Ee * Dd], g_b2L[Ee * Dd];
__device__ __align__(16) __half g_aggH[Nn * 4 * Dd], g_aggL[Nn * 4 * Dd];
__device__ int g_cnt[Nn];
__device__ int g_off[Nn + 1];
__device__ int g_cur[Nn];
__device__ int g_csr[Ee];
#define WT_LAYER 557056
__device__ __align__(16) __half g_wT[2 * WT_LAYER];

__device__ __forceinline__ float gelu_f(float x) {
    return 0.5f * x * (1.0f + erff(x * 0.70710678118654752f));
}
__device__ __forceinline__ uint32_t smem_u32(const void* p) {
    uint32_t a;
    asm("{ .reg .u64 t; cvta.to.shared.u64 t, %1; cvt.u32.u64 %0, t; }" : "=r"(a) : "l"(p));
    return a;
}
__device__ __forceinline__ void ldsm4(uint32_t* r, uint32_t addr) {
    asm volatile("ldmatrix.sync.aligned.m8n8.x4.shared.b16 {%0,%1,%2,%3}, [%4];"
                 : "=r"(r[0]), "=r"(r[1]), "=r"(r[2]), "=r"(r[3]) : "r"(addr));
}
__device__ __forceinline__ void mma16816(float* d, const uint32_t* a, const uint32_t* b) {
    asm volatile("mma.sync.aligned.m16n8k16.row.col.f32.f16.f16.f32 "
                 "{%0,%1,%2,%3}, {%4,%5,%6,%7}, {%8,%9}, {%0,%1,%2,%3};"
                 : "+f"(d[0]), "+f"(d[1]), "+f"(d[2]), "+f"(d[3])
                 : "r"(a[0]), "r"(a[1]), "r"(a[2]), "r"(a[3]), "r"(b[0]), "r"(b[1]));
}
__device__ __forceinline__ void split2h(float x, __half& h, __half& l) {
    h = __float2half_rn(x);
    l = __float2half_rn(x - __half2float(h));
}
__device__ __forceinline__ uint32_t packh(__half a, __half b) {
    return ((uint32_t)__half_as_ushort(b) << 16) | __half_as_ushort(a);
}
__device__ __forceinline__ void cp16(uint32_t saddr, const void* g) {
    asm volatile("cp.async.ca.shared.global [%0], [%1], 16;" :: "r"(saddr), "l"(g));
}
#define CP_COMMIT() asm volatile("cp.async.commit_group;" ::: "memory")
#define CP_WAIT1()  asm volatile("cp.async.wait_group 1;" ::: "memory")
#define CP_WAIT0()  asm volatile("cp.async.wait_group 0;" ::: "memory")

// ---------------- HMMA GEMM, fp16 2-pass, 3-stage cp.async pipeline ----------------
#define PITCH 80
#define ARR 10240
#define BUFSTR 30720
#define SM_PART 92160
#define SM_TOTAL 93184

__global__ void __launch_bounds__(256) gemm_tc(
    int M, int K,
    const __half* __restrict__ AhG, const __half* __restrict__ AlG,
    const __half* __restrict__ BT,
    const float* __restrict__ bias,
    float* __restrict__ Cout,
    __half* __restrict__ CoH, __half* __restrict__ CoL, int ldc,
    int act, int featMode, int outSplit,
    const __half* __restrict__ ndH, const __half* __restrict__ ndL,
    const __half* __restrict__ eaH, const __half* __restrict__ eaL,
    const int* __restrict__ srcI, const int* __restrict__ snkI,
    const float* __restrict__ aAv, const float* __restrict__ aAb)
{
    extern __shared__ char sm[];
    const uint32_t sb = smem_u32(sm);
    const int tid = threadIdx.x, wid = tid >> 5, lane = tid & 31;
    const int m0 = blockIdx.y * 128, n0 = blockIdx.x * 128, z = blockIdx.z;
    if (act == 2) {
        size_t zo = (size_t)z * K * 128;
        BT += zo; bias += z * 128; aAv += z * 128;
    }
    const int mrow0 = (wid & 3) * 32;
    const int ncol0 = (wid >> 2) * 64;
    const int rowoff = ((lane >> 3) & 1) * 8 + (lane & 7);
    const int coloff = (lane >> 4) * 8;

    const int lr0 = tid >> 2, lg0 = (tid & 3) << 3;
    const int lr1 = (tid + 256) >> 2, lg1 = ((tid + 256) & 3) << 3;

    // hoisted per-slot row index + (featMode) gather indices
    int mm0 = m0 + lr0; if (mm0 >= M) mm0 = M - 1;
    int mm1 = m0 + lr1; if (mm1 >= M) mm1 = M - 1;
    int s0 = 0, t0 = 0, s1 = 0, t1 = 0;
    if (featMode) {
        s0 = srcI[mm0]; t0 = snkI[mm0];
        s1 = srcI[mm1]; t1 = snkI[mm1];
    }

    auto issue_chunk = [&](int c) {
        const uint32_t bb = sb + (uint32_t)(c % 3) * BUFSTR;
        const int k0 = c << 5;
#pragma unroll
        for (int it = 0; it < 2; ++it) {
            int r = it ? lr1 : lr0, g = it ? lg1 : lg0;
            int mm = it ? mm1 : mm0;
            int kg = k0 + g;
            const __half *ph, *pl;
            if (!featMode) { ph = AhG + (size_t)mm * K + kg; pl = AlG + (size_t)mm * K + kg; }
            else if (kg < 128) { int s = it ? s1 : s0; ph = ndH + (size_t)s * 128 + kg; pl = ndL + (size_t)s * 128 + kg; }
            else if (kg < 256) { int s = it ? t1 : t0; ph = ndH + (size_t)s * 128 + (kg - 128); pl = ndL + (size_t)s * 128 + (kg - 128); }
            else { ph = eaH + (size_t)mm * 128 + (kg - 256); pl = eaL + (size_t)mm * 128 + (kg - 256); }
            uint32_t off = (uint32_t)(r * PITCH + g * 2);
            cp16(bb + off, ph);
            cp16(bb + ARR + off, pl);
        }
#pragma unroll
        for (int it = 0; it < 2; ++it) {
            int r = it ? lr1 : lr0, g = it ? lg1 : lg0;
            size_t so = (size_t)(n0 + r) * K + k0 + g;
            uint32_t off = (uint32_t)(r * PITCH + g * 2);
            cp16(bb + 2 * ARR + off, BT + so);
        }
        CP_COMMIT();
    };

    float acc[2][8][4];
#pragma unroll
    for (int i = 0; i < 2; i++)
#pragma unroll
        for (int j = 0; j < 8; j++)
#pragma unroll
            for (int q = 0; q < 4; q++) acc[i][j][q] = 0.f;

    const int nCh = K >> 5;
    issue_chunk(0);
    if (nCh > 1) issue_chunk(1);
    for (int c = 0; c < nCh; ++c) {
        if (c + 1 < nCh) CP_WAIT1();
        else CP_WAIT0();
        __syncthreads();
        const uint32_t bb = sb + (uint32_t)(c % 3) * BUFSTR;
#pragma unroll
        for (int ks = 0; ks < 2; ++ks) {
            const uint32_t kb = (uint32_t)((ks * 16 + coloff) * 2);
            uint32_t ah[2][4], al[2][4];
#pragma unroll
            for (int ma = 0; ma < 2; ++ma) {
                uint32_t ro = (uint32_t)((mrow0 + ma * 16 + rowoff) * PITCH) + kb;
                ldsm4(ah[ma], bb + ro);
                ldsm4(al[ma], bb + ARR + ro);
            }
            uint32_t bh[8][2];
#pragma unroll
            for (int ng = 0; ng < 4; ++ng) {
                uint32_t ro = (uint32_t)((ncol0 + ng * 16 + rowoff) * PITCH) + kb;
                uint32_t t[4];
                ldsm4(t, bb + 2 * ARR + ro);
                bh[2 * ng][0] = t[0]; bh[2 * ng][1] = t[2];
                bh[2 * ng + 1][0] = t[1]; bh[2 * ng + 1][1] = t[3];
            }
#pragma unroll
            for (int ma = 0; ma < 2; ++ma)
#pragma unroll
                for (int na = 0; na < 8; ++na) mma16816(acc[ma][na], ah[ma], bh[na]);
#pragma unroll
            for (int ma = 0; ma < 2; ++ma)
#pragma unroll
                for (int na = 0; na < 8; ++na) mma16816(acc[ma][na], al[ma], bh[na]);
        }
        if (c + 2 < nCh) issue_chunk(c + 2);
    }

    // ---- epilogue ----
    float (*part)[2] = (float(*)[2])(sm + SM_PART);
    const int qr = lane >> 2, qc = (lane & 3) * 2;
    if (act == 2) {
        const int nh = wid >> 2;
        float s[2][2] = {{0.f, 0.f}, {0.f, 0.f}};
#pragma unroll
        for (int ma = 0; ma < 2; ++ma)
#pragma unroll
            for (int na = 0; na < 8; ++na) {
                int n = ncol0 + na * 8 + qc;
#pragma unroll
                for (int j = 0; j < 2; ++j) {
                    float v0 = acc[ma][na][j] + bias[n + j];
                    v0 = v0 > 0.f ? v0 : 0.2f * v0;
                    s[ma][0] += v0 * aAv[n + j];
                    float v1 = acc[ma][na][2 + j] + bias[n + j];
                    v1 = v1 > 0.f ? v1 : 0.2f * v1;
                    s[ma][1] += v1 * aAv[n + j];
                }
            }
#pragma unroll
        for (int ma = 0; ma < 2; ++ma)
#pragma unroll
            for (int g = 0; g < 2; ++g) {
                s[ma][g] += __shfl_xor_sync(0xffffffffu, s[ma][g], 1);
                s[ma][g] += __shfl_xor_sync(0xffffffffu, s[ma][g], 2);
            }
        __syncthreads();
        if ((lane & 3) == 0) {
#pragma unroll
            for (int ma = 0; ma < 2; ++ma) {
                part[mrow0 + ma * 16 + qr][nh] = s[ma][0];
                part[mrow0 + ma * 16 + 8 + qr][nh] = s[ma][1];
            }
        }
        __syncthreads();
        if (tid < 128) {
            int m = m0 + tid;
            if (m < M) Cout[(size_t)m * 4 + z] = part[tid][0] + part[tid][1] + aAb[z];
        }
        return;
    }
#pragma unroll
    for (int ma = 0; ma < 2; ++ma) {
        int mA = m0 + mrow0 + ma * 16 + qr;
        int mB = mA + 8;
#pragma unroll
        for (int na = 0; na < 8; ++na) {
            int n = n0 + ncol0 + na * 8 + qc;
            float2 oA, oB;
            oA.x = acc[ma][na][0] + bias[n];
            oA.y = acc[ma][na][1] + bias[n + 1];
            oB.x = acc[ma][na][2] + bias[n];
            oB.y = acc[ma][na][3] + bias[n + 1];
            if (act == 1) {
                oA.x = gelu_f(oA.x); oA.y = gelu_f(oA.y);
                oB.x = gelu_f(oB.x); oB.y = gelu_f(oB.y);
            }
            if (outSplit) {
                __half h0, l0, h1, l1;
                if (mA < M) {
                    split2h(oA.x, h0, l0); split2h(oA.y, h1, l1);
                    *(uint32_t*)(CoH + (size_t)mA * ldc + n) = packh(h0, h1);
                    *(uint32_t*)(CoL + (size_t)mA * ldc + n) = packh(l0, l1);
                }
                if (mB < M) {
                    split2h(oB.x, h0, l0); split2h(oB.y, h1, l1);
                    *(uint32_t*)(CoH + (size_t)mB * ldc + n) = packh(h0, h1);
                    *(uint32_t*)(CoL + (size_t)mB * ldc + n) = packh(l0, l1);
                }
            } else {
                if (mA < M) *(float2*)(Cout + (size_t)mA * ldc + n) = oA;
                if (mB < M) *(float2*)(Cout + (size_t)mB * ldc + n) = oB;
            }
        }
    }
}

// ---------------- weight transpose to fp16 ----------------
struct TEnt { const float* src; int dstOff; int K; int N; };
struct TTab { TEnt e[26]; };
__global__ void tsplit_k(TTab tab) {
    TEnt E = tab.e[blockIdx.y];
    int i = blockIdx.x * 256 + threadIdx.x;
    int total = E.K * E.N;
    if (i >= total) return;
    int k = i / E.N, n = i % E.N;
    g_wT[E.dstOff + (size_t)n * E.K + k] = __float2half_rn(E.src[i]);
}

// ---------------- setup ----------------
__global__ void embed_k(const int* __restrict__ seq, const float* __restrict__ emb) {
    int i = blockIdx.x * 256 + threadIdx.x;
    if (i < Nn * 128) {
        int nidx = i >> 7, d = i & 127;
        float x = emb[seq[nidx] * 128 + d];
        g_nodes[i] = x;
        __half h, l;
        split2h(x, h, l);
        g_nodesH[i] = h; g_nodesL[i] = l;
    }
}
__global__ void rbf_k(const float* __restrict__ dist, const float* __restrict__ W,
                      const float* __restrict__ b) {
    __shared__ float r[16];
    int e = blockIdx.x;
    int t = threadIdx.x;
    if (t < 16) {
        float mu = 2.0f + (20.0f / 15.0f) * (float)t;
        float x = (dist[e] - mu) * (1.0f / 1.25f);
        r[t] = expf(-x * x) + 1e-8f;
    }
    __syncthreads();
    float s = b[t];
#pragma unroll
    for (int j = 0; j < 16; j++) s += r[j] * W[j * 128 + t];
    long long i = (long long)e * 128 + t;
    g_eattr[i] = s;
    __half h, l;
    split2h(s, h, l);
    g_eatH[i] = h; g_eatL[i] = l;
}

// ---------------- CSR ----------------
__global__ void zero_cnt_k() {
    int i = blockIdx.x * 256 + threadIdx.x;
    if (i < Nn) g_cnt[i] = 0;
}
__global__ void count_k(const int* __restrict__ snk) {
    int e = blockIdx.x * 256 + threadIdx.x;
    if (e < Ee) atomicAdd(&g_cnt[snk[e]], 1);
}
__global__ void __launch_bounds__(1024) scan_k() {
    __shared__ int s[1024];
    int t = threadIdx.x;
    const int CH = (Nn + 1023) / 1024;
    int st = t * CH;
    int en = st + CH; if (en > Nn) en = Nn; if (st > Nn) st = Nn;
    int loc = 0;
    for (int i = st; i < en; i++) loc += g_cnt[i];
    s[t] = loc;
    __syncthreads();
    for (int d = 1; d < 1024; d <<= 1) {
        int v = (t >= d) ? s[t - d] : 0;
        __syncthreads();
        s[t] += v;
        __syncthreads();
    }
    int run = (t == 0) ? 0 : s[t - 1];
    for (int i = st; i < en; i++) {
        g_off[i] = run; g_cur[i] = run; run += g_cnt[i];
    }
    if (t == 1023) g_off[Nn] = s[1023];
}
__global__ void place_k(const int* __restrict__ snk) {
    int e = blockIdx.x * 256 + threadIdx.x;
    if (e < Ee) {
        int p = atomicAdd(&g_cur[snk[e]], 1);
        g_csr[p] = e;
    }
}

// ---------------- per-node softmax + aggregation ----------------
__global__ void __launch_bounds__(128) agg_k() {
    __shared__ float red[4][128];
    int n = blockIdx.x, t = threadIdx.x;
    int beg = g_off[n], end = g_off[n + 1];
    const float4* sc4 = (const float4*)g_scores;

    float mx[4] = {-1e30f, -1e30f, -1e30f, -1e30f};
    for (int i = beg + t; i < end; i += 128) {
        float4 s = sc4[g_csr[i]];
        mx[0] = fmaxf(mx[0], s.x); mx[1] = fmaxf(mx[1], s.y);
        mx[2] = fmaxf(mx[2], s.z); mx[3] = fmaxf(mx[3], s.w);
    }
#pragma unroll
    for (int h = 0; h < 4; h++) red[h][t] = mx[h];
    __syncthreads();
    for (int s = 64; s > 0; s >>= 1) {
        if (t < s)
#pragma unroll
            for (int h = 0; h < 4; h++) red[h][t] = fmaxf(red[h][t], red[h][t + s]);
        __syncthreads();
    }
    float mxf[4];
#pragma unroll
    for (int h = 0; h < 4; h++) mxf[h] = red[h][0];
    __syncthreads();

    float sm[4] = {0.f, 0.f, 0.f, 0.f};
    for (int i = beg + t; i < end; i += 128) {
        float4 s = sc4[g_csr[i]];
        sm[0] += expf(s.x - mxf[0]) + 1e-12f;
        sm[1] += expf(s.y - mxf[1]) + 1e-12f;
        sm[2] += expf(s.z - mxf[2]) + 1e-12f;
        sm[3] += expf(s.w - mxf[3]) + 1e-12f;
    }
#pragma unroll
    for (int h = 0; h < 4; h++) red[h][t] = sm[h];
    __syncthreads();
    for (int s = 64; s > 0; s >>= 1) {
        if (t < s)
#pragma unroll
            for (int h = 0; h < 4; h++) red[h][t] += red[h][t + s];
        __syncthreads();
    }
    float nrm[4];
#pragma unroll
    for (int h = 0; h < 4; h++) nrm[h] = red[h][0];

    float acc[4] = {0.f, 0.f, 0.f, 0.f};
    for (int i = beg; i < end; i++) {
        int e = g_csr[i];
        float4 s = sc4[e];
        float a0 = expf(s.x - mxf[0]) / nrm[0];
        float a1 = expf(s.y - mxf[1]) / nrm[1];
        float a2 = expf(s.z - mxf[2]) / nrm[2];
        float a3 = expf(s.w - mxf[3]) / nrm[3];
        float v = g_nupd[(long long)e * 128 + t];
        acc[0] += a0 * v; acc[1] += a1 * v; acc[2] += a2 * v; acc[3] += a3 * v;
    }
    long long base = (long long)n * 512;
#pragma unroll
    for (int h = 0; h < 4; h++) {
        __half hh, ll;
        split2h(acc[h], hh, ll);
        g_aggH[base + h * 128 + t] = hh;
        g_aggL[base + h * 128 + t] = ll;
    }
}

// ---------------- LayerNorm (+ optional split out) ----------------
__global__ void __launch_bounds__(128) ln_k(const float* __restrict__ a,
                                            const float* __restrict__ r,
                                            const float* __restrict__ g,
                                            const float* __restrict__ b,
                                            float* __restrict__ out,
                                            __half* __restrict__ oh,
                                            __half* __restrict__ ol) {
    int row = blockIdx.x, t = threadIdx.x;
    __shared__ float sh[8];
    long long base = (long long)row * 128;
    float x = a[base + t] + r[base + t];
    float s = x;
#pragma unroll
    for (int o = 16; o; o >>= 1) s += __shfl_xor_sync(0xffffffffu, s, o);
    if ((t & 31) == 0) sh[t >> 5] = s;
    __syncthreads();
    float mean = (sh[0] + sh[1] + sh[2] + sh[3]) * (1.0f / 128.0f);
    float d = x - mean;
    float v = d * d;
#pragma unroll
    for (int o = 16; o; o >>= 1) v += __shfl_xor_sync(0xffffffffu, v, o);
    if ((t & 31) == 0) sh[4 + (t >> 5)] = v;
    __syncthreads();
    float var = (sh[4] + sh[5] + sh[6] + sh[7]) * (1.0f / 128.0f);
    float y = d * rsqrtf(var + 1e-5f) * g[t] + b[t];
    out[base + t] = y;
    if (oh) {
        __half hh, ll;
        split2h(y, hh, ll);
        oh[base + t] = hh; ol[base + t] = ll;
    }
}

// ---------------- host ----------------
extern "C" void kernel_launch(void* const* d_in, const int* in_sizes, int n_in,
                              void* d_out, int out_size) {
    const int* seq = (const int*)d_in[0];
    const int* eidx = (const int*)d_in[1];
    const int* srcI = eidx;
    const int* snkI = eidx + Ee;
    const float* dist = (const float*)d_in[2];
    const float* seq_embed = (const float*)d_in[3];
    const float* edge_lin_W = (const float*)d_in[4];
    const float* edge_lin_b = (const float*)d_in[5];
    const float* aW_W = (const float*)d_in[6];
    const float* aW_b = (const float*)d_in[7];
    const float* aA_W = (const float*)d_in[8];
    const float* aA_b = (const float*)d_in[9];
    const float* nmlp_W1 = (const float*)d_in[10];
    const float* nmlp_b1 = (const float*)d_in[11];
    const float* nmlp_W2 = (const float*)d_in[12];
    const float* nmlp_b2 = (const float*)d_in[13];
    const float* nmlp_W3 = (const float*)d_in[14];
    const float* nmlp_b3 = (const float*)d_in[15];
    const float* dmlp_W1 = (const float*)d_in[16];
    const float* dmlp_b1 = (const float*)d_in[17];
    const float* dmlp_W2 = (const float*)d_in[18];
    const float* dmlp_b2 = (const float*)d_in[19];
    const float* emlp_W1 = (const float*)d_in[20];
    const float* emlp_b1 = (const float*)d_in[21];
    const float* emlp_W2 = (const float*)d_in[22];
    const float* emlp_b2 = (const float*)d_in[23];
    const float* emlp_W3 = (const float*)d_in[24];
    const float* emlp_b3 = (const float*)d_in[25];
    const float* aggr_W = (const float*)d_in[26];
    const float* aggr_b = (const float*)d_in[27];
    const float* n1_g = (const float*)d_in[28];
    const float* n1_b = (const float*)d_in[29];
    const float* e_g = (const float*)d_in[30];
    const float* e_b = (const float*)d_in[31];

    float *p_nodes, *p_eattr, *p_nupd, *p_scores, *p_upd, *p_dense;
    __half *pW, *pNh, *pNl, *pEh, *pEl, *pB1h, *pB1l, *pB2h, *pB2l, *pAgh, *pAgl;
    cudaGetSymbolAddress((void**)&p_nodes, g_nodes);
    cudaGetSymbolAddress((void**)&p_eattr, g_eattr);
    cudaGetSymbolAddress((void**)&p_nupd, g_nupd);
    cudaGetSymbolAddress((void**)&p_scores, g_scores);
    cudaGetSymbolAddress((void**)&p_upd, g_upd);
    cudaGetSymbolAddress((void**)&p_dense, g_dense);
    cudaGetSymbolAddress((void**)&pW, g_wT);
    cudaGetSymbolAddress((void**)&pNh, g_nodesH);
    cudaGetSymbolAddress((void**)&pNl, g_nodesL);
    cudaGetSymbolAddress((void**)&pEh, g_eatH);
    cudaGetSymbolAddress((void**)&pEl, g_eatL);
    cudaGetSymbolAddress((void**)&pB1h, g_b1H);
    cudaGetSymbolAddress((void**)&pB1l, g_b1L);
    cudaGetSymbolAddress((void**)&pB2h, g_b2H);
    cudaGetSymbolAddress((void**)&pB2l, g_b2L);
    cudaGetSymbolAddress((void**)&pAgh, g_aggH);
    cudaGetSymbolAddress((void**)&pAgl, g_aggL);

    cudaFuncSetAttribute(gemm_tc, cudaFuncAttributeMaxDynamicSharedMemorySize, SM_TOTAL);

    TTab tab;
    {
        int idx = 0;
        for (int l = 0; l < 2; l++) {
            int lb = l * WT_LAYER;
            for (int h = 0; h < 4; h++)
                tab.e[idx++] = { aW_W + (size_t)(l * 4 + h) * 384 * 128, lb + h * 49152, 384, 128 };
            tab.e[idx++] = { nmlp_W1 + (size_t)l * 384 * 128, lb + 196608, 384, 128 };
            tab.e[idx++] = { nmlp_W2 + (size_t)l * 128 * 128, lb + 245760, 128, 128 };
            tab.e[idx++] = { nmlp_W3 + (size_t)l * 128 * 128, lb + 262144, 128, 128 };
            tab.e[idx++] = { aggr_W + (size_t)l * 512 * 128, lb + 278528, 512, 128 };
            tab.e[idx++] = { dmlp_W1 + (size_t)l * 128 * 512, lb + 344064, 128, 512 };
            tab.e[idx++] = { dmlp_W2 + (size_t)l * 512 * 128, lb + 409600, 512, 128 };
            tab.e[idx++] = { emlp_W1 + (size_t)l * 384 * 128, lb + 475136, 384, 128 };
            tab.e[idx++] = { emlp_W2 + (size_t)l * 128 * 128, lb + 524288, 128, 128 };
            tab.e[idx++] = { emlp_W3 + (size_t)l * 128 * 128, lb + 540672, 128, 128 };
        }
    }

    auto gemm = [&](int M, int K, int nTile, int zDim,
                    const __half* Ah, const __half* Al, long long wOff,
                    const float* bias, float* Cp, __half* CoH, __half* CoL,
                    int ldc, int act, int feat, int osplit,
                    const float* aAv, const float* aAb) {
        dim3 g(nTile, (M + 127) / 128, zDim);
        gemm_tc<<<g, 256, SM_TOTAL>>>(M, K, Ah, Al, pW + wOff, bias, Cp, CoH, CoL, ldc,
                                      act, feat, osplit, pNh, pNl, pEh, pEl, srcI, snkI, aAv, aAb);
    };

    tsplit_k<<<dim3(256, 26), 256>>>(tab);
    embed_k<<<(Nn * 128 + 255) / 256, 256>>>(seq, seq_embed);
    rbf_k<<<Ee, 128>>>(dist, edge_lin_W, edge_lin_b);
    zero_cnt_k<<<(Nn + 255) / 256, 256>>>();
    count_k<<<(Ee + 255) / 256, 256>>>(snkI);
    scan_k<<<1, 1024>>>();
    place_k<<<(Ee + 255) / 256, 256>>>(snkI);

    float* outNodes = (float*)d_out;
    float* outEattr = (float*)d_out + (long long)Nn * 128;

    for (int l = 0; l < 2; l++) {
        long long lb = (long long)l * WT_LAYER;
        gemm(Ee, Cc, 1, 4, nullptr, nullptr, lb + 0, aW_b + l * 512,
             p_scores, nullptr, nullptr, 0, 2, 1, 0, aA_W + l * 512, aA_b + l * 4);
        gemm(Ee, Cc, 1, 1, nullptr, nullptr, lb + 196608, nmlp_b1 + l * 128,
             nullptr, pB1h, pB1l, 128, 1, 1, 1, nullptr, nullptr);
        gemm(Ee, 128, 1, 1, pB1h, pB1l, lb + 245760, nmlp_b2 + l * 128,
             nullptr, pB2h, pB2l, 128, 1, 0, 1, nullptr, nullptr);
        gemm(Ee, 128, 1, 1, pB2h, pB2l, lb + 262144, nmlp_b3 + l * 128,
             p_nupd, nullptr, nullptr, 128, 0, 0, 0, nullptr, nullptr);
        agg_k<<<Nn, 128>>>();
        gemm(Nn, 512, 1, 1, pAgh, pAgl, lb + 278528, aggr_b + l * 128,
             p_upd, nullptr, nullptr, 128, 0, 0, 0, nullptr, nullptr);
        ln_k<<<Nn, 128>>>(p_nodes, p_upd, n1_g + l * 128, n1_b + l * 128, p_nodes, pNh, pNl);
        gemm(Nn, 128, 4, 1, pNh, pNl, lb + 344064, dmlp_b1 + l * 512,
             nullptr, pB1h, pB1l, 512, 1, 0, 1, nullptr, nullptr);
        gemm(Nn, 512, 1, 1, pB1h, pB1l, lb + 409600, dmlp_b2 + l * 128,
             p_dense, nullptr, nullptr, 128, 0, 0, 0, nullptr, nullptr);
        // second node LN: at l==1 write fp32 result directly into d_out (emlp uses the fp16 split)
        ln_k<<<Nn, 128>>>(p_dense, p_upd, n1_g + l * 128, n1_b + l * 128,
                          l == 1 ? outNodes : p_nodes, pNh, pNl);
        gemm(Ee, Cc, 1, 1, nullptr, nullptr, lb + 475136, emlp_b1 + l * 128,
             nullptr, pB1h, pB1l, 128, 1, 1, 1, nullptr, nullptr);
        gemm(Ee, 128, 1, 1, pB1h, pB1l, lb + 524288, emlp_b2 + l * 128,
             nullptr, pB2h, pB2l, 128, 1, 0, 1, nullptr, nullptr);
        gemm(Ee, 128, 1, 1, pB2h, pB2l, lb + 540672, emlp_b3 + l * 128,
             p_nupd, nullptr, nullptr, 128, 0, 0, 0, nullptr, nullptr);
        // eattr LN: at l==1 write directly into d_out (nothing downstream needs it)
        ln_k<<<Ee, 128>>>(p_eattr, p_nupd, e_g + l * 128, e_b + l * 128,
                          l == 1 ? outEattr : p_eattr,
                          l == 0 ? pEh : nullptr, l == 0 ? pEl : nullptr);
    }
}